// round 8
// baseline (speedup 1.0000x reference)
#include <cuda_runtime.h>

#define HWc   4096
#define NPIX  16384   // B*H*W
#define Cc    256
#define CPc   32
#define EPSc  1e-5f

__device__ float g_km[NPIX*CPc];
__device__ float g_qm[NPIX*CPc];
__device__ float g_xm[NPIX*CPc];
__device__ float g_pre[NPIX*CPc];
__device__ float g_part[64*1056];
__device__ float g_ab[2*Cc];
__device__ unsigned int g_cnt;   // zero-init; self-resets each call

// ---------------------------------------------------------------------------
// K1: km/qm/xm = conv1x1(x, W) (+bias, km *= vessel), channel-last output
// grid (256 pixel-tiles of 64, 3 matrices), block 256
// ---------------------------------------------------------------------------
__global__ void k1_kqx(const float* __restrict__ x, const float* __restrict__ vessel,
                       const float* __restrict__ wk, const float* __restrict__ bk,
                       const float* __restrict__ wq, const float* __restrict__ bq,
                       const float* __restrict__ wx, const float* __restrict__ bx)
{
    __shared__ __align__(16) float xs[32][64];
    __shared__ __align__(16) float ws[32][32];
    int t  = threadIdx.x;
    int tx = t & 63;          // pixel within tile
    int ty = t >> 6;          // output group of 8 (4 groups -> 32 outs)
    int which = blockIdx.y;
    const float* W  = (which==0) ? wk : (which==1) ? wq : wx;
    const float* Bv = (which==0) ? bk : (which==1) ? bq : bx;
    float* outp     = (which==0) ? g_km : (which==1) ? g_qm : g_xm;

    int p0 = blockIdx.x * 64;
    const float* xb = x + (size_t)(p0 >> 12) * (Cc*HWc) + (p0 & (HWc-1));

    float acc[8];
#pragma unroll
    for (int i = 0; i < 8; ++i) acc[i] = 0.f;

    for (int c0 = 0; c0 < Cc; c0 += 32) {
#pragma unroll
        for (int i = 0; i < 8; ++i) {
            int idx = i*256 + t;
            int cc = idx >> 6, px = idx & 63;
            xs[cc][px] = xb[(size_t)(c0+cc)*HWc + px];
        }
#pragma unroll
        for (int i = 0; i < 4; ++i) {
            int idx = i*256 + t;
            int o = idx >> 5, cc = idx & 31;
            ws[cc][o] = W[o*Cc + c0 + cc];
        }
        __syncthreads();
#pragma unroll
        for (int cc = 0; cc < 32; ++cc) {
            float xv = xs[cc][tx];
            float4 wa = *(const float4*)&ws[cc][ty*8];
            float4 wb = *(const float4*)&ws[cc][ty*8+4];
            acc[0] += wa.x*xv; acc[1] += wa.y*xv; acc[2] += wa.z*xv; acc[3] += wa.w*xv;
            acc[4] += wb.x*xv; acc[5] += wb.y*xv; acc[6] += wb.z*xv; acc[7] += wb.w*xv;
        }
        __syncthreads();
    }
    int p = p0 + tx;
    float scale = (which==0) ? vessel[p] : 1.f;
    float* orow = outp + (size_t)p*CPc + ty*8;
#pragma unroll
    for (int i = 0; i < 8; ++i)
        orow[i] = (acc[i] + Bv[ty*8+i]) * scale;
}

// ---------------------------------------------------------------------------
// K2: multi-scale local attention, fused across nested windows (3<5<7<9).
// NEW lane layout: warp = 16 pixels x 2 lanes/pixel x 16 channels/lane.
// Per offset: 4 LDG.128/lane-half, 16 FMA, ONE shfl, 1 predicated STS, 1 FMAX
// -> overhead amortized over 16 px (was 4). Block = one image row (128 thr,
// 4 warps, 64 px): h-guard is block-uniform, only dx guard per-lane.
// dy loops kept rolled (code-size sensitivity). Pass3 reads premultiplied
// e*coef from smem (no radius logic in hot sweep).
// ---------------------------------------------------------------------------
__global__ void __launch_bounds__(128) k2_attn()
{
    __shared__ float sc[4][81*16];   // per-warp: [j][pixel-in-warp]
    int t    = threadIdx.x;
    int lane = t & 31, warp = t >> 5;
    int pxi  = lane >> 1;           // pixel in warp (0..15)
    int par  = lane & 1;            // channel half (16 ch each)
    int blk  = blockIdx.x;          // row id: b*64 + h
    int h    = blk & 63;
    int w    = warp * 16 + pxi;
    int p    = blk * 64 + w;        // global pixel index
    float* scp = sc[warp];

    const float* qr = g_qm + (size_t)p*CPc + par*16;
    float4 q0 = *(const float4*)(qr+0);
    float4 q1 = *(const float4*)(qr+4);
    float4 q2 = *(const float4*)(qr+8);
    float4 q3 = *(const float4*)(qr+12);

    const float* kmbase = g_km + (size_t)p*CPc + par*16;
    const float* xmbase = g_xm + (size_t)p*CPc + par*16;

    // pass 1: 81 scores (zero-padding => OOB score == 0)
    float m = -1e30f;
#pragma unroll 1
    for (int dy = -4; dy <= 4; ++dy) {
        bool rowok = ((unsigned)(h+dy) < 64u);
        const float* krow = kmbase + dy*64*CPc;
        int jrow = (dy+4)*9;
#pragma unroll
        for (int dx = -4; dx <= 4; ++dx) {
            float s = 0.f;
            if (rowok && ((unsigned)(w+dx) < 64u)) {
                const float* r = krow + dx*CPc;
                float4 a = *(const float4*)(r+0);
                float4 b = *(const float4*)(r+4);
                float4 c = *(const float4*)(r+8);
                float4 d = *(const float4*)(r+12);
                s = a.x*q0.x + a.y*q0.y + a.z*q0.z + a.w*q0.w
                  + b.x*q1.x + b.y*q1.y + b.z*q1.z + b.w*q1.w
                  + c.x*q2.x + c.y*q2.y + c.z*q2.z + c.w*q2.w
                  + d.x*q3.x + d.y*q3.y + d.z*q3.z + d.w*q3.w;
            }
            s += __shfl_xor_sync(0xffffffffu, s, 1);
            if (par == 0) scp[(jrow + dx + 4)*16 + pxi] = s;
            m = fmaxf(m, s);
        }
    }
    __syncwarp();

    // pass 2a: e_j = exp(s_j - m); nested partial sums z1..z4 (Chebyshev radius)
    float z1=0.f, z2=0.f, z3=0.f, z4=0.f;
    for (int j = par; j < 81; j += 2) {
        int jd = j/9; int dy = jd-4, dx = j-jd*9-4;
        float e = __expf(scp[j*16 + pxi] - m);
        scp[j*16 + pxi] = e;
        int a = max(abs(dy), abs(dx));
        z4 += e;
        if (a <= 3) z3 += e;
        if (a <= 2) z2 += e;
        if (a <= 1) z1 += e;
    }
    z1 += __shfl_xor_sync(0xffffffffu, z1, 1);
    z2 += __shfl_xor_sync(0xffffffffu, z2, 1);
    z3 += __shfl_xor_sync(0xffffffffu, z3, 1);
    z4 += __shfl_xor_sync(0xffffffffu, z4, 1);
    float inv1 = 1.0f/z1, inv2 = 1.0f/z2, inv3 = 1.0f/z3, inv4 = 1.0f/z4;
    __syncwarp();

    // pass 2b: premultiply combined coefficient into the buffer
    for (int j = par; j < 81; j += 2) {
        int jd = j/9; int dy = jd-4, dx = j-jd*9-4;
        int a = max(abs(dy), abs(dx));
        float coef = inv4;
        if (a <= 3) coef += inv3;
        if (a <= 2) coef += inv2;
        if (a <= 1) coef += inv1;
        scp[j*16 + pxi] *= coef;
    }
    __syncwarp();

    // pass 3: pure weighted sweep (OOB value == 0 -> skip)
    float4 A0 = make_float4(0.f,0.f,0.f,0.f);
    float4 A1 = A0, A2 = A0, A3 = A0;
#pragma unroll 1
    for (int dy = -4; dy <= 4; ++dy) {
        if ((unsigned)(h+dy) >= 64u) continue;
        const float* xrow = xmbase + dy*64*CPc;
        int jrow = (dy+4)*9;
#pragma unroll
        for (int dx = -4; dx <= 4; ++dx) {
            if ((unsigned)(w+dx) >= 64u) continue;
            float wj = scp[(jrow + dx + 4)*16 + pxi];
            const float* r = xrow + dx*CPc;
            float4 a = *(const float4*)(r+0);
            float4 b = *(const float4*)(r+4);
            float4 c = *(const float4*)(r+8);
            float4 d = *(const float4*)(r+12);
            A0.x += wj*a.x; A0.y += wj*a.y; A0.z += wj*a.z; A0.w += wj*a.w;
            A1.x += wj*b.x; A1.y += wj*b.y; A1.z += wj*b.z; A1.w += wj*b.w;
            A2.x += wj*c.x; A2.y += wj*c.y; A2.z += wj*c.z; A2.w += wj*c.w;
            A3.x += wj*d.x; A3.y += wj*d.y; A3.z += wj*d.z; A3.w += wj*d.w;
        }
    }
    float* op = g_pre + (size_t)p*CPc + par*16;
    *(float4*)(op+0)  = A0;
    *(float4*)(op+4)  = A1;
    *(float4*)(op+8)  = A2;
    *(float4*)(op+12) = A3;
}

// ---------------------------------------------------------------------------
// K3: fused BN-stats. Phase 1 (all 64 blocks): partial mean[32] + S[32][32]
// over a 256-pixel chunk. Phase 2 (last-arriving block, threadfence+counter):
// reduce partials, var_y = w^T S w - (w.mu)^2, fold into per-channel affine.
// ---------------------------------------------------------------------------
__global__ void k3_stats(const float* __restrict__ wf, const float* __restrict__ bf,
                         const float* __restrict__ gamma, const float* __restrict__ beta)
{
    __shared__ __align__(16) float ps[256*32];
    int t = threadIdx.x;
    size_t base = (size_t)blockIdx.x * 256 * 32;
#pragma unroll
    for (int i = 0; i < 32; ++i)
        ps[i*256 + t] = g_pre[base + i*256 + t];
    __syncthreads();

    int i  = t >> 3;
    int j4 = (t & 7) * 4;
    float s0=0.f, s1=0.f, s2=0.f, s3=0.f;
    for (int p = 0; p < 256; ++p) {
        float a  = ps[p*32 + i];
        float4 b = *(const float4*)&ps[p*32 + j4];
        s0 += a*b.x; s1 += a*b.y; s2 += a*b.z; s3 += a*b.w;
    }
    float* part = g_part + blockIdx.x * 1056;
    part[32 + i*32 + j4 + 0] = s0;
    part[32 + i*32 + j4 + 1] = s1;
    part[32 + i*32 + j4 + 2] = s2;
    part[32 + i*32 + j4 + 3] = s3;
    if (t < 32) {
        float mm = 0.f;
        for (int p = 0; p < 256; ++p) mm += ps[p*32 + t];
        part[t] = mm;
    }
    __threadfence();
    __syncthreads();

    __shared__ unsigned int amLast;
    if (t == 0) amLast = atomicAdd(&g_cnt, 1u);
    __syncthreads();
    if (amLast != 63u) return;

    float* S = ps;   // reuse smem
    for (int e = t; e < 1056; e += 256) {
        float s = 0.f;
#pragma unroll
        for (int b = 0; b < 64; ++b) s += g_part[b*1056 + e];
        S[e] = s * (1.0f/16384.0f);
    }
    __syncthreads();

    {
        float wreg[32];
#pragma unroll
        for (int c = 0; c < 32; ++c) wreg[c] = wf[t*32 + c];
        float wmu = 0.f;
#pragma unroll
        for (int c = 0; c < 32; ++c) wmu += wreg[c] * S[c];
        float qf = 0.f;
        for (int c = 0; c < 32; ++c) {
            float tc = 0.f;
#pragma unroll
            for (int d = 0; d < 32; ++d) tc += S[32 + c*32 + d] * wreg[d];
            qf += wreg[c] * tc;
        }
        float var   = qf - wmu*wmu;
        float meanY = wmu + bf[t];
        float a = gamma[t] * rsqrtf(var + EPSc);
        g_ab[t]       = a;
        g_ab[256 + t] = beta[t] - a * meanY;
    }
    if (t == 0) g_cnt = 0u;   // reset for next graph replay
}

// ---------------------------------------------------------------------------
// K4: out = x + a[co]*(wf.pre) + bb[co]  (bb = a*bf + beta - a*meanY, folded)
// grid (128 px-tiles of 128, 4 co-groups of 64), block 128.  (R6 version)
// ---------------------------------------------------------------------------
__global__ void k4_final(const float* __restrict__ x, const float* __restrict__ wf,
                         const float* __restrict__ bf, float* __restrict__ out)
{
    __shared__ __align__(16) float ws[64*32];
    __shared__ float as[64], bbs[64];
    int t = threadIdx.x;
    int cog = blockIdx.y * 64;
#pragma unroll
    for (int i = 0; i < 16; ++i)
        ws[i*128 + t] = wf[cog*32 + i*128 + t];
    if (t < 64) {
        float a = g_ab[cog+t];
        as[t]  = a;
        bbs[t] = g_ab[256+cog+t] + a * bf[cog+t];
    }
    __syncthreads();

    int p = blockIdx.x * 128 + t;
    float pr[32];
#pragma unroll
    for (int c = 0; c < 32; c += 4) {
        float4 v = *(const float4*)(g_pre + (size_t)p*32 + c);
        pr[c]=v.x; pr[c+1]=v.y; pr[c+2]=v.z; pr[c+3]=v.w;
    }
    int b = p >> 12, hw = p & 4095;
    const float* xrow = x   + (size_t)b*(Cc*HWc) + hw;
    float*       orow = out + (size_t)b*(Cc*HWc) + hw;
    for (int co = 0; co < 64; ++co) {
        const float* wr = &ws[co*32];
        float y = 0.f;
#pragma unroll
        for (int c = 0; c < 32; ++c) y += wr[c] * pr[c];
        size_t off = (size_t)(cog + co) * HWc;
        orow[off] = xrow[off] + as[co]*y + bbs[co];
    }
}

// ---------------------------------------------------------------------------
extern "C" void kernel_launch(void* const* d_in, const int* in_sizes, int n_in,
                              void* d_out, int out_size)
{
    const float* x      = (const float*)d_in[0];
    const float* vessel = (const float*)d_in[1];
    const float* wk     = (const float*)d_in[2];
    const float* bk     = (const float*)d_in[3];
    const float* wq     = (const float*)d_in[4];
    const float* bq     = (const float*)d_in[5];
    const float* wx     = (const float*)d_in[6];
    const float* bx     = (const float*)d_in[7];
    const float* wf     = (const float*)d_in[8];
    const float* bf     = (const float*)d_in[9];
    const float* gamma  = (const float*)d_in[10];
    const float* beta   = (const float*)d_in[11];
    float* out = (float*)d_out;

    k1_kqx<<<dim3(256,3), 256>>>(x, vessel, wk, bk, wq, bq, wx, bx);
    k2_attn<<<256, 128>>>();
    k3_stats<<<64, 256>>>(wf, bf, gamma, beta);
    k4_final<<<dim3(128,4), 128>>>(x, wf, bf, out);
}

// round 9
// speedup vs baseline: 1.1992x; 1.1992x over previous
#include <cuda_runtime.h>

#define HWc   4096
#define NPIX  16384   // B*H*W
#define Cc    256
#define CPc   32
#define EPSc  1e-5f

__device__ float g_km[NPIX*CPc];
__device__ float g_qm[NPIX*CPc];
__device__ float g_xm[NPIX*CPc];
__device__ float g_pre[NPIX*CPc];
__device__ float g_part[64*1056];
__device__ float g_ab[2*Cc];
__device__ unsigned int g_cnt;   // zero-init; self-resets each call

// ---------------------------------------------------------------------------
// K1: km/qm/xm = conv1x1(x, W) (+bias, km *= vessel), channel-last output
// grid (256 pixel-tiles of 64, 3 matrices), block 256
// ---------------------------------------------------------------------------
__global__ void k1_kqx(const float* __restrict__ x, const float* __restrict__ vessel,
                       const float* __restrict__ wk, const float* __restrict__ bk,
                       const float* __restrict__ wq, const float* __restrict__ bq,
                       const float* __restrict__ wx, const float* __restrict__ bx)
{
    __shared__ __align__(16) float xs[32][64];
    __shared__ __align__(16) float ws[32][32];
    int t  = threadIdx.x;
    int tx = t & 63;          // pixel within tile
    int ty = t >> 6;          // output group of 8 (4 groups -> 32 outs)
    int which = blockIdx.y;
    const float* W  = (which==0) ? wk : (which==1) ? wq : wx;
    const float* Bv = (which==0) ? bk : (which==1) ? bq : bx;
    float* outp     = (which==0) ? g_km : (which==1) ? g_qm : g_xm;

    int p0 = blockIdx.x * 64;
    const float* xb = x + (size_t)(p0 >> 12) * (Cc*HWc) + (p0 & (HWc-1));

    float acc[8];
#pragma unroll
    for (int i = 0; i < 8; ++i) acc[i] = 0.f;

    for (int c0 = 0; c0 < Cc; c0 += 32) {
#pragma unroll
        for (int i = 0; i < 8; ++i) {
            int idx = i*256 + t;
            int cc = idx >> 6, px = idx & 63;
            xs[cc][px] = xb[(size_t)(c0+cc)*HWc + px];
        }
#pragma unroll
        for (int i = 0; i < 4; ++i) {
            int idx = i*256 + t;
            int o = idx >> 5, cc = idx & 31;
            ws[cc][o] = W[o*Cc + c0 + cc];
        }
        __syncthreads();
#pragma unroll
        for (int cc = 0; cc < 32; ++cc) {
            float xv = xs[cc][tx];
            float4 wa = *(const float4*)&ws[cc][ty*8];
            float4 wb = *(const float4*)&ws[cc][ty*8+4];
            acc[0] += wa.x*xv; acc[1] += wa.y*xv; acc[2] += wa.z*xv; acc[3] += wa.w*xv;
            acc[4] += wb.x*xv; acc[5] += wb.y*xv; acc[6] += wb.z*xv; acc[7] += wb.w*xv;
        }
        __syncthreads();
    }
    int p = p0 + tx;
    float scale = (which==0) ? vessel[p] : 1.f;
    float* orow = outp + (size_t)p*CPc + ty*8;
#pragma unroll
    for (int i = 0; i < 8; ++i)
        orow[i] = (acc[i] + Bv[ty*8+i]) * scale;
}

// ---------------------------------------------------------------------------
// K2: multi-scale local attention, fused across nested windows (3<5<7<9).
// R6 geometry (warp = 4 px, 8 lanes/px, 4 ch/lane; 1024 blocks x 128) with
// pass 2 ELIMINATED:
//  - no max-shift (|s| <~ 30 << 88; ratios shift-invariant; OOB s=0 -> e=1
//    matches zero-padding exactly)
//  - pass 1: after the 8-lane butterfly every lane has s; compute e=exp(s)
//    per-lane, accumulate nested sums z1..z4 locally in registers with
//    compile-time radius; store e to smem (cg==0 lane).
//  - pass 3: wj = e * c_a where c1..c4 are pre-combined 1/z sums, selected
//    at compile time per unrolled offset.
// ---------------------------------------------------------------------------
__global__ void k2_attn()
{
    __shared__ float sc[4][81*4];   // per-warp exp buffer: [j][pixel-in-warp]
    int t    = threadIdx.x;
    int lane = t & 31, warp = t >> 5;
    int pxg  = lane >> 3;           // pixel in warp (0..3)
    int cg   = lane & 7;            // channel group (4 ch each)
    int p  = blockIdx.x * 16 + warp * 4 + pxg;
    int hw = p & (HWc-1);
    int h  = hw >> 6, w = hw & 63;

    const float* kmrow = g_km + (size_t)p*CPc + cg*4;
    const float* xmrow = g_xm + (size_t)p*CPc + cg*4;
    float4 q = *(const float4*)(g_qm + (size_t)p*CPc + cg*4);
    float* scp = sc[warp];

    // pass 1: scores -> e = exp(s), nested z sums in registers
    float z1=0.f, z2=0.f, z3=0.f, z4=0.f;
#pragma unroll
    for (int dy = -4; dy <= 4; ++dy) {
#pragma unroll
        for (int dx = -4; dx <= 4; ++dx) {
            int j = (dy+4)*9 + (dx+4);
            bool ok = ((unsigned)(h+dy) < 64u) && ((unsigned)(w+dx) < 64u);
            float4 km4 = make_float4(0.f,0.f,0.f,0.f);
            if (ok) km4 = *(const float4*)(kmrow + (dy*64+dx)*CPc);
            float s = km4.x*q.x + km4.y*q.y + km4.z*q.z + km4.w*q.w;
            s += __shfl_xor_sync(0xffffffffu, s, 1);
            s += __shfl_xor_sync(0xffffffffu, s, 2);
            s += __shfl_xor_sync(0xffffffffu, s, 4);
            float e = __expf(s);
            if (cg == 0) scp[j*4 + pxg] = e;
            const int ady = (dy < 0) ? -dy : dy;
            const int adx = (dx < 0) ? -dx : dx;
            const int a = (ady > adx) ? ady : adx;   // compile-time constant
            z4 += e;
            if (a <= 3) z3 += e;
            if (a <= 2) z2 += e;
            if (a <= 1) z1 += e;
        }
    }
    __syncwarp();

    float i4 = 1.0f/z4;
    float i3 = 1.0f/z3;
    float i2 = 1.0f/z2;
    float i1 = 1.0f/z1;
    float c4 = i4;
    float c3 = i4 + i3;
    float c2 = i4 + i3 + i2;
    float c1 = i4 + i3 + i2 + i1;

    // pass 3: weighted sweep, coefficient selected at compile time per offset
    float ax=0.f, ay=0.f, az=0.f, aw=0.f;
#pragma unroll
    for (int dy = -4; dy <= 4; ++dy) {
#pragma unroll
        for (int dx = -4; dx <= 4; ++dx) {
            int j = (dy+4)*9 + (dx+4);
            bool ok = ((unsigned)(h+dy) < 64u) && ((unsigned)(w+dx) < 64u);
            if (!ok) continue;   // OOB value == 0
            const int ady = (dy < 0) ? -dy : dy;
            const int adx = (dx < 0) ? -dx : dx;
            const int a = (ady > adx) ? ady : adx;   // compile-time constant
            float coef = (a <= 1) ? c1 : (a == 2) ? c2 : (a == 3) ? c3 : c4;
            float wj = scp[j*4 + pxg] * coef;
            float4 xm4 = *(const float4*)(xmrow + (dy*64+dx)*CPc);
            ax += wj*xm4.x; ay += wj*xm4.y; az += wj*xm4.z; aw += wj*xm4.w;
        }
    }
    *(float4*)(g_pre + (size_t)p*CPc + cg*4) = make_float4(ax, ay, az, aw);
}

// ---------------------------------------------------------------------------
// K3: fused BN-stats. Phase 1 (all 64 blocks): partial mean[32] + S[32][32]
// over a 256-pixel chunk. Phase 2 (last-arriving block, threadfence+counter):
// reduce partials, var_y = w^T S w - (w.mu)^2, fold into per-channel affine.
// ---------------------------------------------------------------------------
__global__ void k3_stats(const float* __restrict__ wf, const float* __restrict__ bf,
                         const float* __restrict__ gamma, const float* __restrict__ beta)
{
    __shared__ __align__(16) float ps[256*32];
    int t = threadIdx.x;
    size_t base = (size_t)blockIdx.x * 256 * 32;
#pragma unroll
    for (int i = 0; i < 32; ++i)
        ps[i*256 + t] = g_pre[base + i*256 + t];
    __syncthreads();

    int i  = t >> 3;
    int j4 = (t & 7) * 4;
    float s0=0.f, s1=0.f, s2=0.f, s3=0.f;
    for (int p = 0; p < 256; ++p) {
        float a  = ps[p*32 + i];
        float4 b = *(const float4*)&ps[p*32 + j4];
        s0 += a*b.x; s1 += a*b.y; s2 += a*b.z; s3 += a*b.w;
    }
    float* part = g_part + blockIdx.x * 1056;
    part[32 + i*32 + j4 + 0] = s0;
    part[32 + i*32 + j4 + 1] = s1;
    part[32 + i*32 + j4 + 2] = s2;
    part[32 + i*32 + j4 + 3] = s3;
    if (t < 32) {
        float mm = 0.f;
        for (int p = 0; p < 256; ++p) mm += ps[p*32 + t];
        part[t] = mm;
    }
    __threadfence();
    __syncthreads();

    __shared__ unsigned int amLast;
    if (t == 0) amLast = atomicAdd(&g_cnt, 1u);
    __syncthreads();
    if (amLast != 63u) return;

    float* S = ps;   // reuse smem
    for (int e = t; e < 1056; e += 256) {
        float s = 0.f;
#pragma unroll
        for (int b = 0; b < 64; ++b) s += g_part[b*1056 + e];
        S[e] = s * (1.0f/16384.0f);
    }
    __syncthreads();

    {
        float wreg[32];
#pragma unroll
        for (int c = 0; c < 32; ++c) wreg[c] = wf[t*32 + c];
        float wmu = 0.f;
#pragma unroll
        for (int c = 0; c < 32; ++c) wmu += wreg[c] * S[c];
        float qf = 0.f;
        for (int c = 0; c < 32; ++c) {
            float tc = 0.f;
#pragma unroll
            for (int d = 0; d < 32; ++d) tc += S[32 + c*32 + d] * wreg[d];
            qf += wreg[c] * tc;
        }
        float var   = qf - wmu*wmu;
        float meanY = wmu + bf[t];
        float a = gamma[t] * rsqrtf(var + EPSc);
        g_ab[t]       = a;
        g_ab[256 + t] = beta[t] - a * meanY;
    }
    if (t == 0) g_cnt = 0u;   // reset for next graph replay
}

// ---------------------------------------------------------------------------
// K4: out = x + a[co]*(wf.pre) + bb[co]  (bb = a*bf + beta - a*meanY, folded)
// grid (128 px-tiles of 128, 4 co-groups of 64), block 128.  (R6 version)
// ---------------------------------------------------------------------------
__global__ void k4_final(const float* __restrict__ x, const float* __restrict__ wf,
                         const float* __restrict__ bf, float* __restrict__ out)
{
    __shared__ __align__(16) float ws[64*32];
    __shared__ float as[64], bbs[64];
    int t = threadIdx.x;
    int cog = blockIdx.y * 64;
#pragma unroll
    for (int i = 0; i < 16; ++i)
        ws[i*128 + t] = wf[cog*32 + i*128 + t];
    if (t < 64) {
        float a = g_ab[cog+t];
        as[t]  = a;
        bbs[t] = g_ab[256+cog+t] + a * bf[cog+t];
    }
    __syncthreads();

    int p = blockIdx.x * 128 + t;
    float pr[32];
#pragma unroll
    for (int c = 0; c < 32; c += 4) {
        float4 v = *(const float4*)(g_pre + (size_t)p*32 + c);
        pr[c]=v.x; pr[c+1]=v.y; pr[c+2]=v.z; pr[c+3]=v.w;
    }
    int b = p >> 12, hw = p & 4095;
    const float* xrow = x   + (size_t)b*(Cc*HWc) + hw;
    float*       orow = out + (size_t)b*(Cc*HWc) + hw;
    for (int co = 0; co < 64; ++co) {
        const float* wr = &ws[co*32];
        float y = 0.f;
#pragma unroll
        for (int c = 0; c < 32; ++c) y += wr[c] * pr[c];
        size_t off = (size_t)(cog + co) * HWc;
        orow[off] = xrow[off] + as[co]*y + bbs[co];
    }
}

// ---------------------------------------------------------------------------
extern "C" void kernel_launch(void* const* d_in, const int* in_sizes, int n_in,
                              void* d_out, int out_size)
{
    const float* x      = (const float*)d_in[0];
    const float* vessel = (const float*)d_in[1];
    const float* wk     = (const float*)d_in[2];
    const float* bk     = (const float*)d_in[3];
    const float* wq     = (const float*)d_in[4];
    const float* bq     = (const float*)d_in[5];
    const float* wx     = (const float*)d_in[6];
    const float* bx     = (const float*)d_in[7];
    const float* wf     = (const float*)d_in[8];
    const float* bf     = (const float*)d_in[9];
    const float* gamma  = (const float*)d_in[10];
    const float* beta   = (const float*)d_in[11];
    float* out = (float*)d_out;

    k1_kqx<<<dim3(256,3), 256>>>(x, vessel, wk, bk, wq, bq, wx, bx);
    k2_attn<<<1024, 128>>>();
    k3_stats<<<64, 256>>>(wf, bf, gamma, beta);
    k4_final<<<dim3(128,4), 128>>>(x, wf, bf, out);
}